// round 11
// baseline (speedup 1.0000x reference)
#include <cuda_runtime.h>
#include <cuda_bf16.h>
#include <cstdint>

// Problem constants: B=4, N=1024, C=256, H=8
#define Cc 256
#define Hh 8
#define ZA 16        // split-K factor for kernel A (deterministic, no atomics)

// Scratch (no allocation allowed -> __device__ globals)
__device__ float g_partial[ZA * Cc * Cc];         // 4 MB split-K partials
__device__ float g_cp[ZA * Cc];                   // c partials per k-split
__device__ float g_c[Cc];                         // folded bias vector
__device__ __nv_bfloat16 g_Wt_hi[Cc * Cc];        // W^T hi split  [j][k]
__device__ __nv_bfloat16 g_Wt_lo[Cc * Cc];        // W^T lo split  [j][k]
// Pre-split operands (written by kP)
__device__ __nv_bfloat16 g_vh[4096 * Cc];         // v hi           [m][k]
__device__ __nv_bfloat16 g_vl[4096 * Cc];         // v lo           [m][k]
__device__ __nv_bfloat16 g_At_hi[Cc * 2048];      // Vr^T hi        [j'][k]
__device__ __nv_bfloat16 g_At_lo[Cc * 2048];      // Vr^T lo        [j'][k]
__device__ __nv_bfloat16 g_Bt_hi[Cc * 2048];      // lin^T hi       [j][k]
__device__ __nv_bfloat16 g_Bt_lo[Cc * 2048];      // lin^T lo       [j][k]

// ---- helpers --------------------------------------------------------------
__device__ __forceinline__ void mma_bf16(float* c, const uint32_t* a,
                                         const uint32_t* b) {
    asm volatile(
        "mma.sync.aligned.m16n8k16.row.col.f32.bf16.bf16.f32 "
        "{%0,%1,%2,%3}, {%4,%5,%6,%7}, {%8,%9}, {%0,%1,%2,%3};"
        : "+f"(c[0]), "+f"(c[1]), "+f"(c[2]), "+f"(c[3])
        : "r"(a[0]), "r"(a[1]), "r"(a[2]), "r"(a[3]), "r"(b[0]), "r"(b[1]));
}
__device__ __forceinline__ uint32_t bf2(float x, float y) {
    __nv_bfloat162 h = __floats2bfloat162_rn(x, y);
    return *(uint32_t*)&h;
}
__device__ __forceinline__ float2 unbf2(uint32_t u) {
    __nv_bfloat162 h = *(__nv_bfloat162*)&u;
    return make_float2(__bfloat162float(h.x), __bfloat162float(h.y));
}
__device__ __forceinline__ uint32_t smem_u32(const void* p) {
    uint32_t a;
    asm("{ .reg .u64 t; cvta.to.shared.u64 t, %1; cvt.u32.u64 %0, t; }"
        : "=r"(a) : "l"(p));
    return a;
}
__device__ __forceinline__ void cpa16(uint32_t dst, const void* src) {
    asm volatile("cp.async.ca.shared.global [%0], [%1], 16;"
                 :: "r"(dst), "l"(src));
}
__device__ __forceinline__ void cpa_commit_wait() {
    asm volatile("cp.async.commit_group;");
    asm volatile("cp.async.wait_group 0;" ::: "memory");
}
// split a float2 into hi/lo bf16x2 words
__device__ __forceinline__ void split2(float x, float y, uint32_t& h, uint32_t& l) {
    h = bf2(x, y);
    float2 f = unbf2(h);
    l = bf2(x - f.x, y - f.y);
}

// ---------------------------------------------------------------------------
// Kernel P: pre-split everything into bf16 hi/lo in fragment-friendly layouts.
//   blocks [0,256):   v -> g_vh/g_vl (flat float2 copy-split)
//   blocks [256,320): V -> g_At_*[j'][k]  (k=i*8+h contiguous at src: pure copy)
//   blocks [320,448): lin -> g_Bt_*[j][k] (64x64 smem tile transpose)
// ---------------------------------------------------------------------------
__global__ __launch_bounds__(256) void kP(const float* __restrict__ v,
                                          const float* __restrict__ V,
                                          const float* __restrict__ lin) {
    __shared__ float T[64][65];
    const int b = blockIdx.x, t = threadIdx.x;

    if (b < 256) {                       // ---- v split: 524288 float2 units
        #pragma unroll
        for (int q = 0; q < 8; ++q) {
            int idx = b * 2048 + t + q * 256;
            float2 xy = ((const float2*)v)[idx];
            uint32_t h, l;
            split2(xy.x, xy.y, h, l);
            *(uint32_t*)&g_vh[idx * 2] = h;
            *(uint32_t*)&g_vl[idx * 2] = l;
        }
    } else if (b < 320) {                // ---- V gather-split: 65536 units
        #pragma unroll
        for (int q = 0; q < 4; ++q) {
            int u = (b - 256) * 1024 + t + q * 256;
            int jp = u & 255, i = u >> 8;
            const float* src = V + i * 2048 + jp * 8;
            float4 a = *(const float4*)src;
            float4 c = *(const float4*)(src + 4);
            uint4 hv, lv;
            split2(a.x, a.y, hv.x, lv.x);
            split2(a.z, a.w, hv.y, lv.y);
            split2(c.x, c.y, hv.z, lv.z);
            split2(c.z, c.w, hv.w, lv.w);
            *(uint4*)&g_At_hi[jp * 2048 + i * 8] = hv;
            *(uint4*)&g_At_lo[jp * 2048 + i * 8] = lv;
        }
    } else {                             // ---- lin transpose-split: 128 tiles
        int tb = b - 320;
        int kt = tb >> 2, jt = tb & 3;   // 32 k-tiles x 4 j-tiles of 64
        #pragma unroll
        for (int q = 0; q < 16; ++q) {
            int item = t + q * 256;
            int kl = item >> 6, jl = item & 63;
            T[kl][jl] = lin[(kt * 64 + kl) * Cc + jt * 64 + jl];
        }
        __syncthreads();
        #pragma unroll
        for (int q = 0; q < 8; ++q) {
            int item = t + q * 256;
            int jl = item >> 5, klp = item & 31;
            uint32_t h, l;
            split2(T[2 * klp][jl], T[2 * klp + 1][jl], h, l);
            *(uint32_t*)&g_Bt_hi[(jt * 64 + jl) * 2048 + kt * 64 + klp * 2] = h;
            *(uint32_t*)&g_Bt_lo[(jt * 64 + jl) * 2048 + kt * 64 + klp * 2] = l;
        }
    }
}

// ---------------------------------------------------------------------------
// Kernel A (HMMA, cp.async staging): partial_z = Vr^T-tile @ lin-tile.
//   CTA 64(j') x 64(j), K=128 (2 chunks of 64). Grid (4, 4, ZA=16).
//   All operands pre-split bf16 with k contiguous -> staging is 8x cp.async
//   16B per thread per chunk. No conversion in-kernel -> low regs, high occ.
// ---------------------------------------------------------------------------
__global__ __launch_bounds__(256) void kA_mma(const float* __restrict__ biasV) {
    __shared__ uint32_t Ah[64][36], Al[64][36];   // [j'][k-pair]
    __shared__ uint32_t Bh[64][36], Bl[64][36];   // [j][k-pair]

    const int t    = threadIdx.x;
    const int w    = t >> 5;
    const int lane = t & 31;
    const int mw   = (w & 3) * 16;
    const int nh   = (w >> 2) * 32;
    const int j0  = blockIdx.x * 64;
    const int jp0 = blockIdx.y * 64;
    const int z   = blockIdx.z;

    const uint32_t sAh = smem_u32(&Ah[0][0]), sAl = smem_u32(&Al[0][0]);
    const uint32_t sBh = smem_u32(&Bh[0][0]), sBl = smem_u32(&Bl[0][0]);

    float acc[4][4] = {};
    float csum = 0.0f;

    #pragma unroll
    for (int kc = 0; kc < 2; ++kc) {
        const int k0 = z * 128 + kc * 64;
        __syncthreads();
        // 4 arrays x 512 ops of 16B; thread does 8.
        #pragma unroll
        for (int it = 0; it < 8; ++it) {
            int ot  = t + it * 256;
            int arr = ot >> 9, o = ot & 511;
            int row = o >> 3, seg = o & 7;
            uint32_t dst;
            const __nv_bfloat16* src;
            if (arr == 0)      { dst = sAh; src = g_At_hi + (jp0 + row) * 2048; }
            else if (arr == 1) { dst = sAl; src = g_At_lo + (jp0 + row) * 2048; }
            else if (arr == 2) { dst = sBh; src = g_Bt_hi + (j0 + row) * 2048; }
            else               { dst = sBl; src = g_Bt_lo + (j0 + row) * 2048; }
            cpa16(dst + row * 144 + seg * 16, src + k0 + seg * 8);
        }
        cpa_commit_wait();
        __syncthreads();

        #pragma unroll
        for (int ks = 0; ks < 4; ++ks) {
            const int row = mw + (lane >> 2);
            const int kk  = ks * 8 + (lane & 3);
            uint32_t ah[4], al[4];
            ah[0] = Ah[row][kk];     ah[1] = Ah[row + 8][kk];
            ah[2] = Ah[row][kk + 4]; ah[3] = Ah[row + 8][kk + 4];
            al[0] = Al[row][kk];     al[1] = Al[row + 8][kk];
            al[2] = Al[row][kk + 4]; al[3] = Al[row + 8][kk + 4];
            #pragma unroll
            for (int nt = 0; nt < 4; ++nt) {
                const int j = nh + nt * 8 + (lane >> 2);
                uint32_t bh[2], bl[2];
                bh[0] = Bh[j][kk]; bh[1] = Bh[j][kk + 4];
                bl[0] = Bl[j][kk]; bl[1] = Bl[j][kk + 4];
                mma_bf16(acc[nt], ah, bh);
                mma_bf16(acc[nt], ah, bl);
                mma_bf16(acc[nt], al, bh);
            }
        }

        // c-partial from staged bf16 lin tile (y==0 blocks only)
        if (blockIdx.y == 0 && t < 64) {
            #pragma unroll 8
            for (int kp = 0; kp < 32; ++kp) {
                float2 bv = *(const float2*)&biasV[k0 + kp * 2];
                float2 hh = unbf2(Bh[t][kp]);
                float2 ll = unbf2(Bl[t][kp]);
                csum = fmaf(bv.x, hh.x + ll.x, csum);
                csum = fmaf(bv.y, hh.y + ll.y, csum);
            }
        }
    }

    const int jr = jp0 + mw + (lane >> 2);
    #pragma unroll
    for (int nt = 0; nt < 4; ++nt) {
        const int j = j0 + nh + nt * 8 + (lane & 3) * 2;
        *(float2*)&g_partial[z * (Cc * Cc) + jr * Cc + j] =
            make_float2(acc[nt][0], acc[nt][1]);
        *(float2*)&g_partial[z * (Cc * Cc) + (jr + 8) * Cc + j] =
            make_float2(acc[nt][2], acc[nt][3]);
    }
    if (blockIdx.y == 0 && t < 64)
        g_cp[z * Cc + j0 + t] = csum;
}

// ---------------------------------------------------------------------------
// Kernel R: reduce split-K partials -> transposed bf16 hi/lo W; reduce c.
// ---------------------------------------------------------------------------
__global__ __launch_bounds__(256) void kR() {
    if (blockIdx.x < 256) {
        int idx = blockIdx.x * 256 + threadIdx.x;
        float s = 0.0f;
        #pragma unroll
        for (int z = 0; z < ZA; ++z)
            s += g_partial[z * (Cc * Cc) + idx];
        int jp = idx >> 8, j = idx & 255;
        __nv_bfloat16 hi = __float2bfloat16_rn(s);
        float lof = s - __bfloat162float(hi);
        g_Wt_hi[j * Cc + jp] = hi;
        g_Wt_lo[j * Cc + jp] = __float2bfloat16_rn(lof);
    } else {
        int j = threadIdx.x;
        float s = 0.0f;
        #pragma unroll
        for (int z = 0; z < ZA; ++z)
            s += g_cp[z * Cc + j];
        g_c[j] = s;
    }
}

// ---------------------------------------------------------------------------
// Kernel B (HMMA, cp.async staging): out = v @ W + c.
//   CTA 64m x 64j, 4 K-chunks of 64; operands pre-split (g_vh/vl, g_Wt_*).
// ---------------------------------------------------------------------------
__global__ __launch_bounds__(256) void kB_mma(float* __restrict__ out) {
    __shared__ uint32_t Ah[64][36], Al[64][36];   // [m][k-pair]
    __shared__ uint32_t Bh[64][36], Bl[64][36];   // [j][k-pair]

    const int t    = threadIdx.x;
    const int w    = t >> 5;
    const int lane = t & 31;
    const int mw   = (w & 3) * 16;
    const int nh   = (w >> 2) * 32;
    const int j0 = blockIdx.x * 64;
    const int m0 = blockIdx.y * 64;

    const uint32_t sAh = smem_u32(&Ah[0][0]), sAl = smem_u32(&Al[0][0]);
    const uint32_t sBh = smem_u32(&Bh[0][0]), sBl = smem_u32(&Bl[0][0]);

    float acc[4][4] = {};

    #pragma unroll
    for (int kc = 0; kc < 4; ++kc) {
        const int k0 = kc * 64;
        __syncthreads();
        #pragma unroll
        for (int it = 0; it < 8; ++it) {
            int ot  = t + it * 256;
            int arr = ot >> 9, o = ot & 511;
            int row = o >> 3, seg = o & 7;
            uint32_t dst;
            const __nv_bfloat16* src;
            if (arr == 0)      { dst = sAh; src = g_vh + (m0 + row) * Cc; }
            else if (arr == 1) { dst = sAl; src = g_vl + (m0 + row) * Cc; }
            else if (arr == 2) { dst = sBh; src = g_Wt_hi + (j0 + row) * Cc; }
            else               { dst = sBl; src = g_Wt_lo + (j0 + row) * Cc; }
            cpa16(dst + row * 144 + seg * 16, src + k0 + seg * 8);
        }
        cpa_commit_wait();
        __syncthreads();

        #pragma unroll
        for (int ks = 0; ks < 4; ++ks) {
            const int row = mw + (lane >> 2);
            const int kk  = ks * 8 + (lane & 3);
            uint32_t ah[4], al[4];
            ah[0] = Ah[row][kk];     ah[1] = Ah[row + 8][kk];
            ah[2] = Ah[row][kk + 4]; ah[3] = Ah[row + 8][kk + 4];
            al[0] = Al[row][kk];     al[1] = Al[row + 8][kk];
            al[2] = Al[row][kk + 4]; al[3] = Al[row + 8][kk + 4];
            #pragma unroll
            for (int nt = 0; nt < 4; ++nt) {
                const int j = nh + nt * 8 + (lane >> 2);
                uint32_t bh[2], bl[2];
                bh[0] = Bh[j][kk]; bh[1] = Bh[j][kk + 4];
                bl[0] = Bl[j][kk]; bl[1] = Bl[j][kk + 4];
                mma_bf16(acc[nt], ah, bh);
                mma_bf16(acc[nt], ah, bl);
                mma_bf16(acc[nt], al, bh);
            }
        }
    }

    const int mrow = m0 + mw + (lane >> 2);
    #pragma unroll
    for (int nt = 0; nt < 4; ++nt) {
        const int j = j0 + nh + nt * 8 + (lane & 3) * 2;
        float2 cj = *(const float2*)&g_c[j];
        *(float2*)&out[mrow * Cc + j] =
            make_float2(acc[nt][0] + cj.x, acc[nt][1] + cj.y);
        *(float2*)&out[(mrow + 8) * Cc + j] =
            make_float2(acc[nt][2] + cj.x, acc[nt][3] + cj.y);
    }
}

// ---------------------------------------------------------------------------
// Inputs (metadata order): q, k, v, bias, atten_mask, Q, K, V,
//                          bias_Q, bias_K, bias_V, linear_output
// softmax over m sums to 1 -> attention is identity on vh; everything folds
// to out = v @ (Vr^T @ lin) + c.
// ---------------------------------------------------------------------------
extern "C" void kernel_launch(void* const* d_in, const int* in_sizes, int n_in,
                              void* d_out, int out_size) {
    const float* v     = (const float*)d_in[2];
    const float* V     = (const float*)d_in[7];
    const float* biasV = (const float*)d_in[10];
    const float* lin   = (const float*)d_in[11];
    float* out = (float*)d_out;

    kP<<<448, 256>>>(v, V, lin);
    kA_mma<<<dim3(4, 4, ZA), 256>>>(biasV);
    kR<<<257, 256>>>();
    kB_mma<<<dim3(4, 64), 256>>>(out);
}

// round 12
// speedup vs baseline: 1.2842x; 1.2842x over previous
#include <cuda_runtime.h>
#include <cuda_bf16.h>
#include <cstdint>

// Problem constants: B=4, N=1024, C=256, H=8
#define Cc 256
#define Hh 8
#define ZA 16        // split-K factor for kernel A (deterministic, no atomics)

// Scratch (no allocation allowed -> __device__ globals)
__device__ float g_partial[ZA * Cc * Cc];         // 4 MB split-K partials
__device__ float g_cp[ZA * Cc];                   // c partials per k-split
__device__ float g_c[Cc];                         // folded bias vector
__device__ __nv_bfloat16 g_Wt_hi[Cc * Cc];        // W^T hi split  [j][k]
__device__ __nv_bfloat16 g_Wt_lo[Cc * Cc];        // W^T lo split  [j][k]
// Pre-split operands (written by kP)
__device__ __nv_bfloat16 g_vh[4096 * Cc];         // v hi           [m][k]
__device__ __nv_bfloat16 g_vl[4096 * Cc];         // v lo           [m][k]
__device__ __nv_bfloat16 g_At_hi[Cc * 2048];      // Vr^T hi        [j'][k]
__device__ __nv_bfloat16 g_At_lo[Cc * 2048];      // Vr^T lo        [j'][k]
__device__ __nv_bfloat16 g_Bt_hi[Cc * 2048];      // lin^T hi       [j][k]
__device__ __nv_bfloat16 g_Bt_lo[Cc * 2048];      // lin^T lo       [j][k]

// ---- helpers --------------------------------------------------------------
__device__ __forceinline__ void mma_bf16(float* c, const uint32_t* a,
                                         const uint32_t* b) {
    asm volatile(
        "mma.sync.aligned.m16n8k16.row.col.f32.bf16.bf16.f32 "
        "{%0,%1,%2,%3}, {%4,%5,%6,%7}, {%8,%9}, {%0,%1,%2,%3};"
        : "+f"(c[0]), "+f"(c[1]), "+f"(c[2]), "+f"(c[3])
        : "r"(a[0]), "r"(a[1]), "r"(a[2]), "r"(a[3]), "r"(b[0]), "r"(b[1]));
}
__device__ __forceinline__ uint32_t bf2(float x, float y) {
    __nv_bfloat162 h = __floats2bfloat162_rn(x, y);
    return *(uint32_t*)&h;
}
__device__ __forceinline__ float2 unbf2(uint32_t u) {
    __nv_bfloat162 h = *(__nv_bfloat162*)&u;
    return make_float2(__bfloat162float(h.x), __bfloat162float(h.y));
}
__device__ __forceinline__ uint32_t smem_u32(const void* p) {
    uint32_t a;
    asm("{ .reg .u64 t; cvta.to.shared.u64 t, %1; cvt.u32.u64 %0, t; }"
        : "=r"(a) : "l"(p));
    return a;
}
__device__ __forceinline__ void cpa16(uint32_t dst, const void* src) {
    asm volatile("cp.async.ca.shared.global [%0], [%1], 16;"
                 :: "r"(dst), "l"(src));
}
__device__ __forceinline__ void cpa_commit() {
    asm volatile("cp.async.commit_group;");
}
template <int N>
__device__ __forceinline__ void cpa_wait() {
    asm volatile("cp.async.wait_group %0;" :: "n"(N) : "memory");
}
__device__ __forceinline__ void split2(float x, float y, uint32_t& h, uint32_t& l) {
    h = bf2(x, y);
    float2 f = unbf2(h);
    l = bf2(x - f.x, y - f.y);
}

// ---------------------------------------------------------------------------
// Kernel P: pre-split everything into bf16 hi/lo in fragment-friendly layouts.
//   blocks [0,256):   v -> g_vh/g_vl (flat float2 copy-split)
//   blocks [256,320): V -> g_At_*[j'][k]  (k=i*8+h contiguous at src)
//   blocks [320,448): lin -> g_Bt_*[j][k] (64x64 smem tile transpose)
// ---------------------------------------------------------------------------
__global__ __launch_bounds__(256) void kP(const float* __restrict__ v,
                                          const float* __restrict__ V,
                                          const float* __restrict__ lin) {
    __shared__ float T[64][65];
    const int b = blockIdx.x, t = threadIdx.x;

    if (b < 256) {                       // ---- v split
        #pragma unroll
        for (int q = 0; q < 8; ++q) {
            int idx = b * 2048 + t + q * 256;
            float2 xy = ((const float2*)v)[idx];
            uint32_t h, l;
            split2(xy.x, xy.y, h, l);
            *(uint32_t*)&g_vh[idx * 2] = h;
            *(uint32_t*)&g_vl[idx * 2] = l;
        }
    } else if (b < 320) {                // ---- V gather-split
        #pragma unroll
        for (int q = 0; q < 4; ++q) {
            int u = (b - 256) * 1024 + t + q * 256;
            int jp = u & 255, i = u >> 8;
            const float* src = V + i * 2048 + jp * 8;
            float4 a = *(const float4*)src;
            float4 c = *(const float4*)(src + 4);
            uint4 hv, lv;
            split2(a.x, a.y, hv.x, lv.x);
            split2(a.z, a.w, hv.y, lv.y);
            split2(c.x, c.y, hv.z, lv.z);
            split2(c.z, c.w, hv.w, lv.w);
            *(uint4*)&g_At_hi[jp * 2048 + i * 8] = hv;
            *(uint4*)&g_At_lo[jp * 2048 + i * 8] = lv;
        }
    } else {                             // ---- lin transpose-split
        int tb = b - 320;
        int kt = tb >> 2, jt = tb & 3;
        #pragma unroll
        for (int q = 0; q < 16; ++q) {
            int item = t + q * 256;
            int kl = item >> 6, jl = item & 63;
            T[kl][jl] = lin[(kt * 64 + kl) * Cc + jt * 64 + jl];
        }
        __syncthreads();
        #pragma unroll
        for (int q = 0; q < 8; ++q) {
            int item = t + q * 256;
            int jl = item >> 5, klp = item & 31;
            uint32_t h, l;
            split2(T[2 * klp][jl], T[2 * klp + 1][jl], h, l);
            *(uint32_t*)&g_Bt_hi[(jt * 64 + jl) * 2048 + kt * 64 + klp * 2] = h;
            *(uint32_t*)&g_Bt_lo[(jt * 64 + jl) * 2048 + kt * 64 + klp * 2] = l;
        }
    }
}

// ---------------------------------------------------------------------------
// Kernel A (HMMA, double-buffered cp.async): partial_z = Vr^T-tile @ lin-tile.
//   CTA 64(j') x 64(j), K=128 (4 chunks of 32, 2-stage pipeline).
//   Grid (4, 4, ZA=16). Smem S[stage][arr][64][20]: stride 20 u32 -> fragment
//   loads (20*row + kk) cover all 32 banks (20r mod 32 walks multiples of 4).
// ---------------------------------------------------------------------------
__global__ __launch_bounds__(256) void kA_mma(const float* __restrict__ biasV) {
    __shared__ uint32_t S[2][4][64][20];          // 40 KB

    const int t    = threadIdx.x;
    const int w    = t >> 5;
    const int lane = t & 31;
    const int mw   = (w & 3) * 16;
    const int nh   = (w >> 2) * 32;
    const int j0  = blockIdx.x * 64;
    const int jp0 = blockIdx.y * 64;
    const int z   = blockIdx.z;

    const uint32_t sS = smem_u32(&S[0][0][0][0]);

    float acc[4][4] = {};
    float csum = 0.0f;

    auto issue = [&](int kc, int st) {
        const int k0 = z * 128 + kc * 32;
        #pragma unroll
        for (int it = 0; it < 4; ++it) {
            int ot  = t + it * 256;
            int arr = ot >> 8;                    // uniform per it
            int o   = ot & 255;
            int row = o >> 2, seg = o & 3;
            const __nv_bfloat16* src =
                (arr == 0) ? g_At_hi + (jp0 + row) * 2048 :
                (arr == 1) ? g_At_lo + (jp0 + row) * 2048 :
                (arr == 2) ? g_Bt_hi + (j0 + row) * 2048 :
                             g_Bt_lo + (j0 + row) * 2048;
            cpa16(sS + ((st * 4 + arr) * 64 + row) * 80 + seg * 16,
                  src + k0 + seg * 8);
        }
        cpa_commit();
    };

    issue(0, 0);
    #pragma unroll
    for (int kc = 0; kc < 4; ++kc) {
        const int st = kc & 1;
        if (kc + 1 < 4) { issue(kc + 1, st ^ 1); cpa_wait<1>(); }
        else            { cpa_wait<0>(); }
        __syncthreads();

        #pragma unroll
        for (int ks = 0; ks < 2; ++ks) {
            const int row = mw + (lane >> 2);
            const int kk  = ks * 8 + (lane & 3);
            uint32_t ah[4], al[4];
            ah[0] = S[st][0][row][kk];     ah[1] = S[st][0][row + 8][kk];
            ah[2] = S[st][0][row][kk + 4]; ah[3] = S[st][0][row + 8][kk + 4];
            al[0] = S[st][1][row][kk];     al[1] = S[st][1][row + 8][kk];
            al[2] = S[st][1][row][kk + 4]; al[3] = S[st][1][row + 8][kk + 4];
            #pragma unroll
            for (int nt = 0; nt < 4; ++nt) {
                const int j = nh + nt * 8 + (lane >> 2);
                uint32_t bh[2], bl[2];
                bh[0] = S[st][2][j][kk]; bh[1] = S[st][2][j][kk + 4];
                bl[0] = S[st][3][j][kk]; bl[1] = S[st][3][j][kk + 4];
                mma_bf16(acc[nt], ah, bh);
                mma_bf16(acc[nt], ah, bl);
                mma_bf16(acc[nt], al, bh);
            }
        }

        // c-partial from staged bf16 lin tile (y==0 blocks only)
        if (blockIdx.y == 0 && t < 64) {
            const int k0 = z * 128 + kc * 32;
            #pragma unroll
            for (int kp = 0; kp < 16; ++kp) {
                float2 bv = *(const float2*)&biasV[k0 + kp * 2];
                float2 hh = unbf2(S[st][2][t][kp]);
                float2 ll = unbf2(S[st][3][t][kp]);
                csum = fmaf(bv.x, hh.x + ll.x, csum);
                csum = fmaf(bv.y, hh.y + ll.y, csum);
            }
        }
        __syncthreads();    // all reads of buffer st done before it refills
    }

    const int jr = jp0 + mw + (lane >> 2);
    #pragma unroll
    for (int nt = 0; nt < 4; ++nt) {
        const int j = j0 + nh + nt * 8 + (lane & 3) * 2;
        *(float2*)&g_partial[z * (Cc * Cc) + jr * Cc + j] =
            make_float2(acc[nt][0], acc[nt][1]);
        *(float2*)&g_partial[z * (Cc * Cc) + (jr + 8) * Cc + j] =
            make_float2(acc[nt][2], acc[nt][3]);
    }
    if (blockIdx.y == 0 && t < 64)
        g_cp[z * Cc + j0 + t] = csum;
}

// ---------------------------------------------------------------------------
// Kernel R: reduce split-K partials -> transposed bf16 hi/lo W; reduce c.
// ---------------------------------------------------------------------------
__global__ __launch_bounds__(256) void kR() {
    if (blockIdx.x < 256) {
        int idx = blockIdx.x * 256 + threadIdx.x;
        float s = 0.0f;
        #pragma unroll
        for (int z = 0; z < ZA; ++z)
            s += g_partial[z * (Cc * Cc) + idx];
        int jp = idx >> 8, j = idx & 255;
        __nv_bfloat16 hi = __float2bfloat16_rn(s);
        float lof = s - __bfloat162float(hi);
        g_Wt_hi[j * Cc + jp] = hi;
        g_Wt_lo[j * Cc + jp] = __float2bfloat16_rn(lof);
    } else {
        int j = threadIdx.x;
        float s = 0.0f;
        #pragma unroll
        for (int z = 0; z < ZA; ++z)
            s += g_cp[z * Cc + j];
        g_c[j] = s;
    }
}

// ---------------------------------------------------------------------------
// Kernel B (HMMA, double-buffered cp.async): out = v @ W + c.
//   CTA 64m x 64j, K=256 (8 chunks of 32, 2-stage pipeline). Grid (4, 64).
// ---------------------------------------------------------------------------
__global__ __launch_bounds__(256) void kB_mma(float* __restrict__ out) {
    __shared__ uint32_t S[2][4][64][20];          // 40 KB

    const int t    = threadIdx.x;
    const int w    = t >> 5;
    const int lane = t & 31;
    const int mw   = (w & 3) * 16;
    const int nh   = (w >> 2) * 32;
    const int j0 = blockIdx.x * 64;
    const int m0 = blockIdx.y * 64;

    const uint32_t sS = smem_u32(&S[0][0][0][0]);

    float acc[4][4] = {};

    auto issue = [&](int kc, int st) {
        const int k0 = kc * 32;
        #pragma unroll
        for (int it = 0; it < 4; ++it) {
            int ot  = t + it * 256;
            int arr = ot >> 8;
            int o   = ot & 255;
            int row = o >> 2, seg = o & 3;
            const __nv_bfloat16* src =
                (arr == 0) ? g_vh + (m0 + row) * Cc :
                (arr == 1) ? g_vl + (m0 + row) * Cc :
                (arr == 2) ? g_Wt_hi + (j0 + row) * Cc :
                             g_Wt_lo + (j0 + row) * Cc;
            cpa16(sS + ((st * 4 + arr) * 64 + row) * 80 + seg * 16,
                  src + k0 + seg * 8);
        }
        cpa_commit();
    };

    issue(0, 0);
    #pragma unroll
    for (int kc = 0; kc < 8; ++kc) {
        const int st = kc & 1;
        if (kc + 1 < 8) { issue(kc + 1, st ^ 1); cpa_wait<1>(); }
        else            { cpa_wait<0>(); }
        __syncthreads();

        #pragma unroll
        for (int ks = 0; ks < 2; ++ks) {
            const int row = mw + (lane >> 2);
            const int kk  = ks * 8 + (lane & 3);
            uint32_t ah[4], al[4];
            ah[0] = S[st][0][row][kk];     ah[1] = S[st][0][row + 8][kk];
            ah[2] = S[st][0][row][kk + 4]; ah[3] = S[st][0][row + 8][kk + 4];
            al[0] = S[st][1][row][kk];     al[1] = S[st][1][row + 8][kk];
            al[2] = S[st][1][row][kk + 4]; al[3] = S[st][1][row + 8][kk + 4];
            #pragma unroll
            for (int nt = 0; nt < 4; ++nt) {
                const int j = nh + nt * 8 + (lane >> 2);
                uint32_t bh[2], bl[2];
                bh[0] = S[st][2][j][kk]; bh[1] = S[st][2][j][kk + 4];
                bl[0] = S[st][3][j][kk]; bl[1] = S[st][3][j][kk + 4];
                mma_bf16(acc[nt], ah, bh);
                mma_bf16(acc[nt], ah, bl);
                mma_bf16(acc[nt], al, bh);
            }
        }
        __syncthreads();
    }

    const int mrow = m0 + mw + (lane >> 2);
    #pragma unroll
    for (int nt = 0; nt < 4; ++nt) {
        const int j = j0 + nh + nt * 8 + (lane & 3) * 2;
        float2 cj = *(const float2*)&g_c[j];
        *(float2*)&out[mrow * Cc + j] =
            make_float2(acc[nt][0] + cj.x, acc[nt][1] + cj.y);
        *(float2*)&out[(mrow + 8) * Cc + j] =
            make_float2(acc[nt][2] + cj.x, acc[nt][3] + cj.y);
    }
}

// ---------------------------------------------------------------------------
// Inputs (metadata order): q, k, v, bias, atten_mask, Q, K, V,
//                          bias_Q, bias_K, bias_V, linear_output
// softmax over m sums to 1 -> attention is identity on vh; everything folds
// to out = v @ (Vr^T @ lin) + c.
// ---------------------------------------------------------------------------
extern "C" void kernel_launch(void* const* d_in, const int* in_sizes, int n_in,
                              void* d_out, int out_size) {
    const float* v     = (const float*)d_in[2];
    const float* V     = (const float*)d_in[7];
    const float* biasV = (const float*)d_in[10];
    const float* lin   = (const float*)d_in[11];
    float* out = (float*)d_out;

    kP<<<448, 256>>>(v, V, lin);
    kA_mma<<<dim3(4, 4, ZA), 256>>>(biasV);
    kR<<<257, 256>>>();
    kB_mma<<<dim3(4, 64), 256>>>(out);
}

// round 13
// speedup vs baseline: 1.4129x; 1.1002x over previous
#include <cuda_runtime.h>
#include <cuda_bf16.h>
#include <cstdint>

// Problem constants: B=4, N=1024, C=256, H=8
#define Cc 256
#define Hh 8
#define ZA 16        // split-K factor for kernel A (deterministic, no atomics)

// Scratch (no allocation allowed -> __device__ globals)
__device__ float g_partial[ZA * Cc * Cc];         // 4 MB split-K partials
__device__ float g_cp[ZA * Cc];                   // c partials per k-split
__device__ float g_c[Cc];                         // folded bias vector
__device__ __nv_bfloat16 g_Wt_hi[Cc * Cc];        // W^T hi split  [j][k]
__device__ __nv_bfloat16 g_Wt_lo[Cc * Cc];        // W^T lo split  [j][k]
// Pre-split operands (written by kP)
__device__ __nv_bfloat16 g_vh[4096 * Cc];         // v hi           [m][k]
__device__ __nv_bfloat16 g_vl[4096 * Cc];         // v lo           [m][k]
__device__ __nv_bfloat16 g_At_hi[Cc * 2048];      // Vr^T hi        [j'][k]
__device__ __nv_bfloat16 g_At_lo[Cc * 2048];      // Vr^T lo        [j'][k]
__device__ __nv_bfloat16 g_Bt_hi[Cc * 2048];      // lin^T hi       [j][k]
__device__ __nv_bfloat16 g_Bt_lo[Cc * 2048];      // lin^T lo       [j][k]

// ---- helpers --------------------------------------------------------------
__device__ __forceinline__ void mma_bf16(float* c, const uint32_t* a,
                                         const uint32_t* b) {
    asm volatile(
        "mma.sync.aligned.m16n8k16.row.col.f32.bf16.bf16.f32 "
        "{%0,%1,%2,%3}, {%4,%5,%6,%7}, {%8,%9}, {%0,%1,%2,%3};"
        : "+f"(c[0]), "+f"(c[1]), "+f"(c[2]), "+f"(c[3])
        : "r"(a[0]), "r"(a[1]), "r"(a[2]), "r"(a[3]), "r"(b[0]), "r"(b[1]));
}
__device__ __forceinline__ uint32_t bf2(float x, float y) {
    __nv_bfloat162 h = __floats2bfloat162_rn(x, y);
    return *(uint32_t*)&h;
}
__device__ __forceinline__ float2 unbf2(uint32_t u) {
    __nv_bfloat162 h = *(__nv_bfloat162*)&u;
    return make_float2(__bfloat162float(h.x), __bfloat162float(h.y));
}
__device__ __forceinline__ uint32_t smem_u32(const void* p) {
    uint32_t a;
    asm("{ .reg .u64 t; cvta.to.shared.u64 t, %1; cvt.u32.u64 %0, t; }"
        : "=r"(a) : "l"(p));
    return a;
}
__device__ __forceinline__ void cpa16(uint32_t dst, const void* src) {
    asm volatile("cp.async.ca.shared.global [%0], [%1], 16;"
                 :: "r"(dst), "l"(src));
}
__device__ __forceinline__ void cpa_commit() {
    asm volatile("cp.async.commit_group;");
}
template <int N>
__device__ __forceinline__ void cpa_wait() {
    asm volatile("cp.async.wait_group %0;" :: "n"(N) : "memory");
}
__device__ __forceinline__ void split2(float x, float y, uint32_t& h, uint32_t& l) {
    h = bf2(x, y);
    float2 f = unbf2(h);
    l = bf2(x - f.x, y - f.y);
}

// ---------------------------------------------------------------------------
// Kernel P: pre-split everything into bf16 hi/lo in fragment-friendly layouts.
// ---------------------------------------------------------------------------
__global__ __launch_bounds__(256) void kP(const float* __restrict__ v,
                                          const float* __restrict__ V,
                                          const float* __restrict__ lin) {
    __shared__ float T[64][65];
    const int b = blockIdx.x, t = threadIdx.x;

    if (b < 256) {                       // ---- v split
        #pragma unroll
        for (int q = 0; q < 8; ++q) {
            int idx = b * 2048 + t + q * 256;
            float2 xy = ((const float2*)v)[idx];
            uint32_t h, l;
            split2(xy.x, xy.y, h, l);
            *(uint32_t*)&g_vh[idx * 2] = h;
            *(uint32_t*)&g_vl[idx * 2] = l;
        }
    } else if (b < 320) {                // ---- V gather-split
        #pragma unroll
        for (int q = 0; q < 4; ++q) {
            int u = (b - 256) * 1024 + t + q * 256;
            int jp = u & 255, i = u >> 8;
            const float* src = V + i * 2048 + jp * 8;
            float4 a = *(const float4*)src;
            float4 c = *(const float4*)(src + 4);
            uint4 hv, lv;
            split2(a.x, a.y, hv.x, lv.x);
            split2(a.z, a.w, hv.y, lv.y);
            split2(c.x, c.y, hv.z, lv.z);
            split2(c.z, c.w, hv.w, lv.w);
            *(uint4*)&g_At_hi[jp * 2048 + i * 8] = hv;
            *(uint4*)&g_At_lo[jp * 2048 + i * 8] = lv;
        }
    } else {                             // ---- lin transpose-split
        int tb = b - 320;
        int kt = tb >> 2, jt = tb & 3;
        #pragma unroll
        for (int q = 0; q < 16; ++q) {
            int item = t + q * 256;
            int kl = item >> 6, jl = item & 63;
            T[kl][jl] = lin[(kt * 64 + kl) * Cc + jt * 64 + jl];
        }
        __syncthreads();
        #pragma unroll
        for (int q = 0; q < 8; ++q) {
            int item = t + q * 256;
            int jl = item >> 5, klp = item & 31;
            uint32_t h, l;
            split2(T[2 * klp][jl], T[2 * klp + 1][jl], h, l);
            *(uint32_t*)&g_Bt_hi[(jt * 64 + jl) * 2048 + kt * 64 + klp * 2] = h;
            *(uint32_t*)&g_Bt_lo[(jt * 64 + jl) * 2048 + kt * 64 + klp * 2] = l;
        }
    }
}

// ---------------------------------------------------------------------------
// Kernel A (HMMA, double-buffered cp.async, 3 accumulators for ILP).
//   CTA 64(j') x 64(j), K=128 (4 chunks of 32). Grid (4, 4, ZA=16).
// ---------------------------------------------------------------------------
__global__ __launch_bounds__(256) void kA_mma(const float* __restrict__ biasV) {
    __shared__ uint32_t S[2][4][64][20];          // 40 KB

    const int t    = threadIdx.x;
    const int w    = t >> 5;
    const int lane = t & 31;
    const int mw   = (w & 3) * 16;
    const int nh   = (w >> 2) * 32;
    const int j0  = blockIdx.x * 64;
    const int jp0 = blockIdx.y * 64;
    const int z   = blockIdx.z;

    const uint32_t sS = smem_u32(&S[0][0][0][0]);

    float acc[4][4] = {}, acc2[4][4] = {}, acc3[4][4] = {};
    float csum = 0.0f;

    auto issue = [&](int kc, int st) {
        const int k0 = z * 128 + kc * 32;
        #pragma unroll
        for (int it = 0; it < 4; ++it) {
            int ot  = t + it * 256;
            int arr = ot >> 8;
            int o   = ot & 255;
            int row = o >> 2, seg = o & 3;
            const __nv_bfloat16* src =
                (arr == 0) ? g_At_hi + (jp0 + row) * 2048 :
                (arr == 1) ? g_At_lo + (jp0 + row) * 2048 :
                (arr == 2) ? g_Bt_hi + (j0 + row) * 2048 :
                             g_Bt_lo + (j0 + row) * 2048;
            cpa16(sS + ((st * 4 + arr) * 64 + row) * 80 + seg * 16,
                  src + k0 + seg * 8);
        }
        cpa_commit();
    };

    issue(0, 0);
    #pragma unroll
    for (int kc = 0; kc < 4; ++kc) {
        const int st = kc & 1;
        if (kc + 1 < 4) { issue(kc + 1, st ^ 1); cpa_wait<1>(); }
        else            { cpa_wait<0>(); }
        __syncthreads();

        #pragma unroll
        for (int ks = 0; ks < 2; ++ks) {
            const int row = mw + (lane >> 2);
            const int kk  = ks * 8 + (lane & 3);
            uint32_t ah[4], al[4];
            ah[0] = S[st][0][row][kk];     ah[1] = S[st][0][row + 8][kk];
            ah[2] = S[st][0][row][kk + 4]; ah[3] = S[st][0][row + 8][kk + 4];
            al[0] = S[st][1][row][kk];     al[1] = S[st][1][row + 8][kk];
            al[2] = S[st][1][row][kk + 4]; al[3] = S[st][1][row + 8][kk + 4];
            #pragma unroll
            for (int nt = 0; nt < 4; ++nt) {
                const int j = nh + nt * 8 + (lane >> 2);
                uint32_t bh[2], bl[2];
                bh[0] = S[st][2][j][kk]; bh[1] = S[st][2][j][kk + 4];
                bl[0] = S[st][3][j][kk]; bl[1] = S[st][3][j][kk + 4];
                mma_bf16(acc[nt],  ah, bh);
                mma_bf16(acc2[nt], ah, bl);
                mma_bf16(acc3[nt], al, bh);
            }
        }

        if (blockIdx.y == 0 && t < 64) {
            const int k0 = z * 128 + kc * 32;
            #pragma unroll
            for (int kp = 0; kp < 16; ++kp) {
                float2 bv = *(const float2*)&biasV[k0 + kp * 2];
                float2 hh = unbf2(S[st][2][t][kp]);
                float2 ll = unbf2(S[st][3][t][kp]);
                csum = fmaf(bv.x, hh.x + ll.x, csum);
                csum = fmaf(bv.y, hh.y + ll.y, csum);
            }
        }
        __syncthreads();
    }

    const int jr = jp0 + mw + (lane >> 2);
    #pragma unroll
    for (int nt = 0; nt < 4; ++nt) {
        const int j = j0 + nh + nt * 8 + (lane & 3) * 2;
        *(float2*)&g_partial[z * (Cc * Cc) + jr * Cc + j] =
            make_float2(acc[nt][0] + acc2[nt][0] + acc3[nt][0],
                        acc[nt][1] + acc2[nt][1] + acc3[nt][1]);
        *(float2*)&g_partial[z * (Cc * Cc) + (jr + 8) * Cc + j] =
            make_float2(acc[nt][2] + acc2[nt][2] + acc3[nt][2],
                        acc[nt][3] + acc2[nt][3] + acc3[nt][3]);
    }
    if (blockIdx.y == 0 && t < 64)
        g_cp[z * Cc + j0 + t] = csum;
}

// ---------------------------------------------------------------------------
// Kernel R: reduce split-K partials -> transposed bf16 hi/lo W; reduce c.
// ---------------------------------------------------------------------------
__global__ __launch_bounds__(256) void kR() {
    if (blockIdx.x < 256) {
        int idx = blockIdx.x * 256 + threadIdx.x;
        float s = 0.0f;
        #pragma unroll
        for (int z = 0; z < ZA; ++z)
            s += g_partial[z * (Cc * Cc) + idx];
        int jp = idx >> 8, j = idx & 255;
        __nv_bfloat16 hi = __float2bfloat16_rn(s);
        float lof = s - __bfloat162float(hi);
        g_Wt_hi[j * Cc + jp] = hi;
        g_Wt_lo[j * Cc + jp] = __float2bfloat16_rn(lof);
    } else {
        int j = threadIdx.x;
        float s = 0.0f;
        #pragma unroll
        for (int z = 0; z < ZA; ++z)
            s += g_cp[z * Cc + j];
        g_c[j] = s;
    }
}

// ---------------------------------------------------------------------------
// Kernel B (HMMA): out = v @ W + c. CTA 64m x 64j, K=256 in 4 chunks of 64,
// 2-stage cp.async double buffer (72 KB dynamic smem), 3 accumulators.
// Smem layout SS(st,arr,row,col): stride 36 u32 -> (36r+k) mod 32 = (4r+k)
// covers 32 banks across a fragment load. Grid (4, 64).
// ---------------------------------------------------------------------------
#define KB_STRIDE 36
#define KB_SMEM (2 * 4 * 64 * KB_STRIDE * 4)     // 73728 B

__global__ __launch_bounds__(256) void kB_mma(float* __restrict__ out) {
    extern __shared__ uint32_t S[];

    const int t    = threadIdx.x;
    const int w    = t >> 5;
    const int lane = t & 31;
    const int mw   = (w & 3) * 16;
    const int nh   = (w >> 2) * 32;
    const int j0 = blockIdx.x * 64;
    const int m0 = blockIdx.y * 64;

    const uint32_t sS = smem_u32(S);
    auto SS = [&](int st, int arr, int row, int col) -> uint32_t& {
        return S[((st * 4 + arr) * 64 + row) * KB_STRIDE + col];
    };

    float acc[4][4] = {}, acc2[4][4] = {}, acc3[4][4] = {};

    auto issue = [&](int kc, int st) {
        const int k0 = kc * 64;
        #pragma unroll
        for (int it = 0; it < 8; ++it) {
            int ot  = t + it * 256;               // 0..2047
            int arr = ot >> 9;
            int o   = ot & 511;
            int row = o >> 3, seg = o & 7;        // 8 segs of 16B = 64 bf16
            const __nv_bfloat16* src =
                (arr == 0) ? g_vh + (m0 + row) * Cc :
                (arr == 1) ? g_vl + (m0 + row) * Cc :
                (arr == 2) ? g_Wt_hi + (j0 + row) * Cc :
                             g_Wt_lo + (j0 + row) * Cc;
            cpa16(sS + ((st * 4 + arr) * 64 + row) * (KB_STRIDE * 4) + seg * 16,
                  src + k0 + seg * 8);
        }
        cpa_commit();
    };

    issue(0, 0);
    #pragma unroll
    for (int kc = 0; kc < 4; ++kc) {
        const int st = kc & 1;
        if (kc + 1 < 4) { issue(kc + 1, st ^ 1); cpa_wait<1>(); }
        else            { cpa_wait<0>(); }
        __syncthreads();

        #pragma unroll
        for (int ks = 0; ks < 4; ++ks) {
            const int row = mw + (lane >> 2);
            const int kk  = ks * 8 + (lane & 3);
            uint32_t ah[4], al[4];
            ah[0] = SS(st, 0, row, kk);     ah[1] = SS(st, 0, row + 8, kk);
            ah[2] = SS(st, 0, row, kk + 4); ah[3] = SS(st, 0, row + 8, kk + 4);
            al[0] = SS(st, 1, row, kk);     al[1] = SS(st, 1, row + 8, kk);
            al[2] = SS(st, 1, row, kk + 4); al[3] = SS(st, 1, row + 8, kk + 4);
            #pragma unroll
            for (int nt = 0; nt < 4; ++nt) {
                const int j = nh + nt * 8 + (lane >> 2);
                uint32_t bh[2], bl[2];
                bh[0] = SS(st, 2, j, kk); bh[1] = SS(st, 2, j, kk + 4);
                bl[0] = SS(st, 3, j, kk); bl[1] = SS(st, 3, j, kk + 4);
                mma_bf16(acc[nt],  ah, bh);
                mma_bf16(acc2[nt], ah, bl);
                mma_bf16(acc3[nt], al, bh);
            }
        }
        __syncthreads();
    }

    const int mrow = m0 + mw + (lane >> 2);
    #pragma unroll
    for (int nt = 0; nt < 4; ++nt) {
        const int j = j0 + nh + nt * 8 + (lane & 3) * 2;
        float2 cj = *(const float2*)&g_c[j];
        *(float2*)&out[mrow * Cc + j] = make_float2(
            acc[nt][0] + acc2[nt][0] + acc3[nt][0] + cj.x,
            acc[nt][1] + acc2[nt][1] + acc3[nt][1] + cj.y);
        *(float2*)&out[(mrow + 8) * Cc + j] = make_float2(
            acc[nt][2] + acc2[nt][2] + acc3[nt][2] + cj.x,
            acc[nt][3] + acc2[nt][3] + acc3[nt][3] + cj.y);
    }
}

// ---------------------------------------------------------------------------
// Inputs (metadata order): q, k, v, bias, atten_mask, Q, K, V,
//                          bias_Q, bias_K, bias_V, linear_output
// softmax over m sums to 1 -> attention is identity on vh; everything folds
// to out = v @ (Vr^T @ lin) + c.
// ---------------------------------------------------------------------------
extern "C" void kernel_launch(void* const* d_in, const int* in_sizes, int n_in,
                              void* d_out, int out_size) {
    const float* v     = (const float*)d_in[2];
    const float* V     = (const float*)d_in[7];
    const float* biasV = (const float*)d_in[10];
    const float* lin   = (const float*)d_in[11];
    float* out = (float*)d_out;

    // Host-side attribute set: not a stream op, capture-safe, deterministic.
    cudaFuncSetAttribute(kB_mma, cudaFuncAttributeMaxDynamicSharedMemorySize,
                         KB_SMEM);

    kP<<<448, 256>>>(v, V, lin);
    kA_mma<<<dim3(4, 4, ZA), 256>>>(biasV);
    kR<<<257, 256>>>();
    kB_mma<<<dim3(4, 64), 256, KB_SMEM>>>(out);
}